// round 4
// baseline (speedup 1.0000x reference)
#include <cuda_runtime.h>
#include <math_constants.h>

#define CCH 32
#define HH  256
#define WW  512
#define KK  10
#define HWPIX (HH*WW)

// Transposed [H,W,C] copy of right (channels contiguous) — static scratch.
__device__ float g_right_t[HWPIX * CCH];

// [C,H,W] -> [H,W,C] for right only.
__global__ void transpose_chw_hwc(const float* __restrict__ right) {
    __shared__ float tile[32][33];
    const int h  = blockIdx.y;
    const int w0 = blockIdx.x * 32;
    const int tx = threadIdx.x, ty = threadIdx.y;
    tile[ty][tx] = right[ty * HWPIX + h * WW + w0 + tx];
    __syncthreads();
    g_right_t[(h * WW + w0 + ty) * CCH + tx] = tile[tx][ty];
}

// Broadcast offset plane p (0..9 = ox[k], 10..19 = oy[k]) within 8-lane group.
#define BCAST(p) __shfl_sync(0xffffffffu, ((p) < 8 ? o0 : ((p) < 16 ? o1 : o2)), \
                             (lane & 24) | ((p) & 7))

__global__ __launch_bounds__(256, 6) void eval_kernel(
    const float* __restrict__ left,
    const float* __restrict__ offx,
    const float* __restrict__ offy,
    float* __restrict__ out)
{
    const int lane = threadIdx.x & 31;
    const int j    = lane & 7;                      // lane within pixel-group
    const int warp = threadIdx.x >> 5;
    const int pix  = blockIdx.x * 32 + warp * 4 + (lane >> 3);
    const int h = pix >> 9;
    const int w = pix & (WW - 1);

    // left channels 4j..4j+3 (strided scalar loads from original [C,H,W])
    const float lv0 = left[(4*j + 0) * HWPIX + pix];
    const float lv1 = left[(4*j + 1) * HWPIX + pix];
    const float lv2 = left[(4*j + 2) * HWPIX + pix];
    const float lv3 = left[(4*j + 3) * HWPIX + pix];

    // 20 offset planes distributed over the 8-lane group: lane j holds planes j, j+8, j+16
    const float o0 = offx[j * HWPIX + pix];
    const float o1 = (j < 2) ? offx[(j + 8) * HWPIX + pix]
                             : offy[(j - 2) * HWPIX + pix];
    const float o2 = (j < 4) ? offy[(j + 6) * HWPIX + pix] : 0.0f;

    const float4* __restrict__ rt = (const float4*)g_right_t;
    const float wf = (float)WW, hf = (float)HH;
    const float wfl = (float)w, hfl = (float)h;

    // online-softmax state
    float m = -CUDART_INF_F;
    float denom = 0.0f, oxa = 0.0f, oya = 0.0f;

    #pragma unroll
    for (int k = 0; k < KK; k++) {
        const float ox_k = BCAST(k);
        const float oy_k = BCAST(k + KK);

        // clip->normalize->unnormalize == rx-0.5 exactly in fp32
        const float rx = fminf(fmaxf(wfl - ox_k, 0.0f), wf - 1.0f);
        const float ry = fminf(fmaxf(hfl - oy_k, 0.0f), hf - 1.0f);
        const float ix = rx - 0.5f;
        const float iy = ry - 0.5f;

        const float x0f = floorf(ix), y0f = floorf(iy);
        const int x0 = (int)x0f, y0 = (int)y0f;          // x0 in [-1,510], y0 in [-1,254]
        const float wx1 = ix - x0f;
        const float wy1 = iy - y0f;
        float wx0 = 1.0f - wx1;
        float wy0 = 1.0f - wy1;
        const bool px = (x0 >= 0);                       // only low edge can be invalid
        const bool py = (y0 >= 0);
        if (!px) wx0 = 0.0f;
        if (!py) wy0 = 0.0f;
        const int x0c = px ? x0 : 0;
        const int y0c = py ? y0 : 0;

        const float w00 = wx0 * wy0, w01 = wx1 * wy0;
        const float w10 = wx0 * wy1, w11 = wx1 * wy1;

        // corner addresses: x1/y1 alias the clamped corner when weight is 0
        const int i00 = (((y0c << 9) + x0c) << 3) + j;
        const int dX  = px ? 8 : 0;
        const int dY  = py ? (WW * 8) : 0;
        const float4 g00 = rt[i00];
        const float4 g01 = rt[i00 + dX];
        const float4 g10 = rt[i00 + dY];
        const float4 g11 = rt[i00 + dX + dY];

        float d;
        {
            float t0 = w00*g00.x + w01*g01.x + w10*g10.x + w11*g11.x;
            float t1 = w00*g00.y + w01*g01.y + w10*g10.y + w11*g11.y;
            float t2 = w00*g00.z + w01*g01.z + w10*g10.z + w11*g11.z;
            float t3 = w00*g00.w + w01*g01.w + w10*g10.w + w11*g11.w;
            d = fabsf(lv0 - t0) + fabsf(lv1 - t1) + fabsf(lv2 - t2) + fabsf(lv3 - t3);
        }

        // reduce over the 8-lane group (serves all 4 pixels of the warp at once)
        d += __shfl_xor_sync(0xffffffffu, d, 4);
        d += __shfl_xor_sync(0xffffffffu, d, 2);
        d += __shfl_xor_sync(0xffffffffu, d, 1);

        const float s = d * (-10000.0f / 32.0f);

        // online softmax step: exactly one of (e, f) differs from 1 and equals
        // exp(-|s - m|); select instead of a second MUFU.
        const float t = __expf(-fabsf(s - m));
        const bool le = (s <= m);
        const float e = le ? t : 1.0f;
        const float f = le ? 1.0f : t;
        m = fmaxf(m, s);
        denom = denom * f + e;
        oxa   = oxa   * f + e * ox_k;
        oya   = oya   * f + e * oy_k;
    }

    if (j == 0) {
        const float inv = __fdividef(1.0f, denom);
        out[pix]         = oxa * inv;
        out[HWPIX + pix] = oya * inv;
    }
}

extern "C" void kernel_launch(void* const* d_in, const int* in_sizes, int n_in,
                              void* d_out, int out_size) {
    const float* left  = (const float*)d_in[0];
    const float* right = (const float*)d_in[1];
    const float* offx  = (const float*)d_in[2];
    const float* offy  = (const float*)d_in[3];
    float* out = (float*)d_out;

    dim3 tb(32, 32);
    dim3 tg(WW / 32, HH);
    transpose_chw_hwc<<<tg, tb>>>(right);

    // 256 threads = 8 warps = 32 pixels per block
    eval_kernel<<<HWPIX / 32, 256>>>(left, offx, offy, out);
}

// round 5
// speedup vs baseline: 1.5544x; 1.5544x over previous
#include <cuda_runtime.h>

#define CCH 32
#define HH  256
#define WW  512
#define KK  10
#define HWPIX (HH*WW)

// Transposed [H,W,C] copy of right (channels contiguous) — static scratch.
__device__ float g_right_t[HWPIX * CCH];

// [C,H,W] -> [H,W,C], float4 on both global sides.
// Block (32,32): covers h fixed, 128 w, all 32 c.
__global__ __launch_bounds__(1024) void transpose_chw_hwc(const float* __restrict__ right) {
    __shared__ float tile[32][129];     // [c][w_local], padded
    const int h  = blockIdx.y;
    const int w0 = blockIdx.x * 128;
    const int tx = threadIdx.x, ty = threadIdx.y;

    // read: thread (tx,ty) -> c=ty, w = w0 + 4tx .. +3 (512B coalesced per warp)
    const float4 v = *(const float4*)(right + (size_t)ty * HWPIX + h * WW + w0 + 4 * tx);
    tile[ty][4*tx + 0] = v.x;
    tile[ty][4*tx + 1] = v.y;
    tile[ty][4*tx + 2] = v.z;
    tile[ty][4*tx + 3] = v.w;
    __syncthreads();

    // write: task t -> w_local = t>>3, cq = t&7; write channels 4cq..4cq+3 at w
    const int t  = ty * 32 + tx;
    const int wl = t >> 3;
    const int cq = t & 7;
    float4 o;
    o.x = tile[4*cq + 0][wl];
    o.y = tile[4*cq + 1][wl];
    o.z = tile[4*cq + 2][wl];
    o.w = tile[4*cq + 3][wl];
    *(float4*)(g_right_t + (size_t)(h * WW + w0 + wl) * CCH + 4 * cq) = o;
}

// Broadcast offset plane p (0..9 = ox[k], 10..19 = oy[k]) within 8-lane group.
#define BCAST(p) __shfl_sync(0xffffffffu, ((p) < 8 ? o0 : ((p) < 16 ? o1 : o2)), \
                             (lane & 24) | ((p) & 7))

__global__ __launch_bounds__(256) void eval_kernel(
    const float* __restrict__ left,
    const float* __restrict__ offx,
    const float* __restrict__ offy,
    float* __restrict__ out)
{
    const int lane = threadIdx.x & 31;
    const int j    = lane & 7;                      // lane within pixel-group
    const int warp = threadIdx.x >> 5;
    const int pix  = blockIdx.x * 32 + warp * 4 + (lane >> 3);
    const int h = pix >> 9;
    const int w = pix & (WW - 1);

    // left channels 4j..4j+3 (strided scalar loads from original [C,H,W])
    const float lv0 = left[(4*j + 0) * HWPIX + pix];
    const float lv1 = left[(4*j + 1) * HWPIX + pix];
    const float lv2 = left[(4*j + 2) * HWPIX + pix];
    const float lv3 = left[(4*j + 3) * HWPIX + pix];

    // 20 offset planes distributed over the 8-lane group: lane j holds planes j, j+8, j+16
    const float o0 = offx[j * HWPIX + pix];
    const float o1 = (j < 2) ? offx[(j + 8) * HWPIX + pix]
                             : offy[(j - 2) * HWPIX + pix];
    const float o2 = (j < 4) ? offy[(j + 6) * HWPIX + pix] : 0.0f;

    const float4* __restrict__ rt = (const float4*)g_right_t;
    const float hf = (float)HH;
    const float wfl = (float)w, hfl = (float)h;
    float s[KK];

    #pragma unroll
    for (int k = 0; k < KK; k++) {
        const float ox_k = BCAST(k);
        const float oy_k = BCAST(k + KK);

        // clip->normalize->unnormalize == rx-0.5 exactly in fp32.
        // offset_x >= 0 so the upper x-clamp (W-1) is a no-op.
        const float rx = fmaxf(wfl - ox_k, 0.0f);
        const float ry = fminf(fmaxf(hfl - oy_k, 0.0f), hf - 1.0f);
        const float ix = rx - 0.5f;
        const float iy = ry - 0.5f;

        const float x0f = floorf(ix), y0f = floorf(iy);
        const int x0 = (int)x0f, y0 = (int)y0f;          // x0 in [-1,510], y0 in [-1,254]
        const float wx1 = ix - x0f;
        const float wy1 = iy - y0f;
        float wx0 = 1.0f - wx1;
        float wy0 = 1.0f - wy1;
        const bool px = (x0 >= 0);                       // only low edge can be invalid
        const bool py = (y0 >= 0);
        if (!px) wx0 = 0.0f;
        if (!py) wy0 = 0.0f;
        const int x0c = px ? x0 : 0;
        const int y0c = py ? y0 : 0;

        const float w00 = wx0 * wy0, w01 = wx1 * wy0;
        const float w10 = wx0 * wy1, w11 = wx1 * wy1;

        // corner addresses: x1/y1 alias the clamped corner when weight is 0
        const int i00 = (((y0c << 9) + x0c) << 3) + j;
        const int dX  = px ? 8 : 0;
        const int dY  = py ? (WW * 8) : 0;
        const float4 g00 = rt[i00];
        const float4 g01 = rt[i00 + dX];
        const float4 g10 = rt[i00 + dY];
        const float4 g11 = rt[i00 + dX + dY];

        float d;
        {
            float t0 = w00*g00.x + w01*g01.x + w10*g10.x + w11*g11.x;
            float t1 = w00*g00.y + w01*g01.y + w10*g10.y + w11*g11.y;
            float t2 = w00*g00.z + w01*g01.z + w10*g10.z + w11*g11.z;
            float t3 = w00*g00.w + w01*g01.w + w10*g10.w + w11*g11.w;
            d = fabsf(lv0 - t0) + fabsf(lv1 - t1) + fabsf(lv2 - t2) + fabsf(lv3 - t3);
        }

        // reduce over the 8-lane group (serves all 4 pixels of the warp at once)
        d += __shfl_xor_sync(0xffffffffu, d, 4);
        d += __shfl_xor_sync(0xffffffffu, d, 2);
        d += __shfl_xor_sync(0xffffffffu, d, 1);

        s[k] = d * (-10000.0f / 32.0f);
    }

    // softmax over K (redundant per lane; iterations independent -> ILP)
    float m = s[0];
    #pragma unroll
    for (int k = 1; k < KK; k++) m = fmaxf(m, s[k]);
    float denom = 0.0f;
    #pragma unroll
    for (int k = 0; k < KK; k++) { s[k] = __expf(s[k] - m); denom += s[k]; }
    const float inv = 1.0f / denom;

    float ox_acc = 0.0f, oy_acc = 0.0f;
    #pragma unroll
    for (int k = 0; k < KK; k++) {
        const float wk = s[k] * inv;
        ox_acc += BCAST(k)      * wk;
        oy_acc += BCAST(k + KK) * wk;
    }

    if (j == 0) {
        out[pix]         = ox_acc;
        out[HWPIX + pix] = oy_acc;
    }
}

extern "C" void kernel_launch(void* const* d_in, const int* in_sizes, int n_in,
                              void* d_out, int out_size) {
    const float* left  = (const float*)d_in[0];
    const float* right = (const float*)d_in[1];
    const float* offx  = (const float*)d_in[2];
    const float* offy  = (const float*)d_in[3];
    float* out = (float*)d_out;

    dim3 tb(32, 32);
    dim3 tg(WW / 128, HH);
    transpose_chw_hwc<<<tg, tb>>>(right);

    // 256 threads = 8 warps = 32 pixels per block
    eval_kernel<<<HWPIX / 32, 256>>>(left, offx, offy, out);
}